// round 8
// baseline (speedup 1.0000x reference)
#include <cuda_runtime.h>
#include <math.h>

#define NT 512
#define PSTR 4352               // padded plane stride (float2)
#define SMEMB (4 * PSTR * 8)    // 139264 bytes

__device__ float2 g_M[2][16];           // [0] = conj(Up) (pass C), [1] = Up (pass R)
__device__ float2 g_T[67108864];        // 512MB scratch: T = X @ U^dagger (complex)

static __device__ __forceinline__ float2 cmul(float2 a, float2 b) {
    return make_float2(a.x * b.x - a.y * b.y, a.x * b.y + a.y * b.x);
}

__global__ void qc_setup(const float* __restrict__ w) {
    const float WM = 0.6324555320336759f;  // sqrt(2/5)
    float h[5];
#pragma unroll
    for (int i = 0; i < 5; i++) h[i] = 0.5f * WM * w[i];
    float c0 = cosf(h[0]), s0 = sinf(h[0]), c1 = cosf(h[1]), s1 = sinf(h[1]);
    float c2 = cosf(h[2]), s2 = sinf(h[2]);
    float A = c1 * c0 - s1 * s0, B = c1 * s0 + s1 * c0;
    float2 M4[4][4];
    for (int i = 0; i < 4; i++)
        for (int j = 0; j < 4; j++) {
            if ((i & 1) != (j & 1)) { M4[i][j] = make_float2(0.f, 0.f); continue; }
            M4[i][j] = ((i >> 1) == (j >> 1)) ? make_float2(A, 0.f) : make_float2(0.f, -B);
        }
    const float yy[4][4] = {{0,0,0,-1},{0,0,1,0},{0,1,0,0},{-1,0,0,0}};
    float2 GM[4][4];
    for (int i = 0; i < 4; i++)
        for (int j = 0; j < 4; j++) {
            float2 acc = make_float2(0.f, 0.f);
            for (int k = 0; k < 4; k++) {
                float2 g = make_float2((i == k) ? c2 : 0.f, -s2 * yy[i][k]);
                float2 p = cmul(g, M4[k][j]);
                acc.x += p.x; acc.y += p.y;
            }
            GM[i][j] = acc;
        }
    float2 e3m = make_float2(cosf(h[3]), -sinf(h[3])), e3p = make_float2(e3m.x, -e3m.y);
    float2 e4m = make_float2(cosf(h[4]), -sinf(h[4])), e4p = make_float2(e4m.x, -e4m.y);
    float2 d[4] = {cmul(e3m, e4m), cmul(e3m, e4p), cmul(e3p, e4m), cmul(e3p, e4p)};
    for (int i = 0; i < 4; i++)
        for (int j = 0; j < 4; j++) {
            float2 up = cmul(d[i], GM[i][j]);
            g_M[1][i * 4 + j] = up;
            g_M[0][i * 4 + j] = make_float2(up.x, -up.y);
        }
}

// contract digit at stride1 (m), then digit at stride4 (n), of v[m+4n]
static __device__ __forceinline__ void stage2(float2 v[16], const float2 M[16]) {
    float2 w[16];
#pragma unroll
    for (int n = 0; n < 4; n++)
#pragma unroll
        for (int o = 0; o < 4; o++) {
            float re = 0.f, im = 0.f;
#pragma unroll
            for (int m = 0; m < 4; m++) {
                float2 u = M[o * 4 + m], x = v[4 * n + m];
                re = fmaf(u.x, x.x, re); re = fmaf(-u.y, x.y, re);
                im = fmaf(u.x, x.y, im); im = fmaf(u.y, x.x, im);
            }
            w[4 * n + o] = make_float2(re, im);
        }
#pragma unroll
    for (int m = 0; m < 4; m++)
#pragma unroll
        for (int o = 0; o < 4; o++) {
            float re = 0.f, im = 0.f;
#pragma unroll
            for (int n = 0; n < 4; n++) {
                float2 u = M[o * 4 + n], x = w[4 * n + m];
                re = fmaf(u.x, x.x, re); re = fmaf(-u.y, x.y, re);
                im = fmaf(u.x, x.y, im); im = fmaf(u.y, x.x, im);
            }
            v[4 * o + m] = make_float2(re, im);
        }
}

// 6 radix-4 stages over 4 planes of 4096 elems in padded smem (pad: L + (L>>4))
static __device__ __forceinline__ void run6(float2* sm, const float2 M[16], int t) {
#pragma unroll 1
    for (int s = t; s < 1024; s += NT) {              // logical strides 1,4
        float2* p = sm + (s >> 8) * PSTR + (s & 255) * 17;
        float2 v[16];
#pragma unroll
        for (int e = 0; e < 16; e++) v[e] = p[e];
        stage2(v, M);
#pragma unroll
        for (int e = 0; e < 16; e++) p[e] = v[e];
    }
    __syncthreads();
#pragma unroll 1
    for (int s = t; s < 1024; s += NT) {              // strides 16,64
        int u = s & 255;
        float2* p = sm + (s >> 8) * PSTR + (u & 15) + 272 * (u >> 4);
        float2 v[16];
#pragma unroll
        for (int e = 0; e < 16; e++) v[e] = p[e * 17];
        stage2(v, M);
#pragma unroll
        for (int e = 0; e < 16; e++) p[e * 17] = v[e];
    }
    __syncthreads();
#pragma unroll 1
    for (int s = t; s < 1024; s += NT) {              // strides 256,1024
        int u = s & 255;
        float2* p = sm + (s >> 8) * PSTR + u + (u >> 4);
        float2 v[16];
#pragma unroll
        for (int e = 0; e < 16; e++) v[e] = p[e * 272];
        stage2(v, M);
#pragma unroll
        for (int e = 0; e < 16; e++) p[e * 272] = v[e];
    }
    __syncthreads();
}

// Pass C: T = X @ U^dagger -> g_T ; tile = 4 rows x 4096 cols, contract col digits
__global__ __launch_bounds__(NT, 1)
void qc_pass_c(const float* __restrict__ X) {
    extern __shared__ float2 sm[];
    int t = threadIdx.x, b = blockIdx.x >> 10, r0 = (blockIdx.x & 1023) << 2;
    float2 M[16];
#pragma unroll
    for (int i = 0; i < 16; i++) M[i] = g_M[0][i];
    const float* Xb = X + ((size_t)(b * 4096 + r0)) * 4096;
#pragma unroll 1
    for (int q = t; q < 4096; q += NT) {              // 4 rows x 1024 float4
        int row = q >> 10, c4 = (q & 1023) << 2;
        float4 f = *(const float4*)(Xb + (size_t)row * 4096 + c4);
        float2* p = sm + row * PSTR + c4 + (c4 >> 4);
        p[0] = make_float2(f.x, 0.f); p[1] = make_float2(f.y, 0.f);
        p[2] = make_float2(f.z, 0.f); p[3] = make_float2(f.w, 0.f);
    }
    __syncthreads();
    run6(sm, M, t);
    float2* Ob = g_T + ((size_t)(b * 4096 + r0)) * 4096;
#pragma unroll 1
    for (int q = t; q < 8192; q += NT) {              // 4 rows x 2048 float2-pairs
        int row = q >> 11, c2 = (q & 2047) << 1;
        float2* p = sm + row * PSTR + c2 + (c2 >> 4);
        *(float4*)(Ob + (size_t)row * 4096 + c2) = make_float4(p[0].x, p[0].y, p[1].x, p[1].y);
    }
}

// Pass R: out = U @ T ; tile = 4096 rows x 4 cols, contract row digits.
// cplx=1: write interleaved complex floats; cplx=0: write real part only.
__global__ __launch_bounds__(NT, 1)
void qc_pass_r(float* __restrict__ out, int cplx) {
    extern __shared__ float2 sm[];
    int t = threadIdx.x, b = blockIdx.x >> 10, c0 = (blockIdx.x & 1023) << 2;
    float2 M[16];
#pragma unroll
    for (int i = 0; i < 16; i++) M[i] = g_M[1][i];
    const float2* Tb = g_T + (size_t)b * 4096 * 4096 + c0;
#pragma unroll 1
    for (int q = t; q < 8192; q += NT) {              // 4096 rows x 2 col-pair halves
        int row = q >> 1, hf = (q & 1) << 1;
        float4 f = *(const float4*)(Tb + (size_t)row * 4096 + hf);
        int pr = row + (row >> 4);
        sm[(hf + 0) * PSTR + pr] = make_float2(f.x, f.y);
        sm[(hf + 1) * PSTR + pr] = make_float2(f.z, f.w);
    }
    __syncthreads();
    run6(sm, M, t);
    if (cplx) {
        float2* Ob = (float2*)out + (size_t)b * 4096 * 4096 + c0;
#pragma unroll 1
        for (int q = t; q < 8192; q += NT) {
            int row = q >> 1, hf = (q & 1) << 1;
            int pr = row + (row >> 4);
            float2 a = sm[(hf + 0) * PSTR + pr], c = sm[(hf + 1) * PSTR + pr];
            *(float4*)(Ob + (size_t)row * 4096 + hf) = make_float4(a.x, a.y, c.x, c.y);
        }
    } else {
        float* Ob = out + (size_t)b * 4096 * 4096 + c0;
#pragma unroll 1
        for (int q = t; q < 4096; q += NT) {
            int row = q, pr = row + (row >> 4);
            *(float4*)(Ob + (size_t)row * 4096) =
                make_float4(sm[0 * PSTR + pr].x, sm[1 * PSTR + pr].x,
                            sm[2 * PSTR + pr].x, sm[3 * PSTR + pr].x);
        }
    }
}

extern "C" void kernel_launch(void* const* d_in, const int* in_sizes, int n_in,
                              void* d_out, int out_size) {
    // Disambiguate inputs by size: x has 4*4096*4096 elements, weight has 5.
    const float* x;
    const float* w;
    if (in_sizes[0] > in_sizes[1]) { x = (const float*)d_in[0]; w = (const float*)d_in[1]; }
    else                           { w = (const float*)d_in[0]; x = (const float*)d_in[1]; }
    int cplx = (out_size >= 134217728) ? 1 : 0;   // complex-as-float32-pairs vs real-only
    cudaFuncSetAttribute(qc_pass_c, cudaFuncAttributeMaxDynamicSharedMemorySize, SMEMB);
    cudaFuncSetAttribute(qc_pass_r, cudaFuncAttributeMaxDynamicSharedMemorySize, SMEMB);
    qc_setup<<<1, 1>>>(w);
    qc_pass_c<<<4096, NT, SMEMB>>>(x);
    qc_pass_r<<<4096, NT, SMEMB>>>((float*)d_out, cplx);
}